// round 14
// baseline (speedup 1.0000x reference)
#include <cuda_runtime.h>
#include <cuda_bf16.h>
#include <math.h>
#include <stdint.h>

// Problem constants
#define BB 32
#define LL 1024
#define EE 512      // H
#define PP 336
#define NLAYERS 3
#define NS 32
#define HH 512
#define H2 1024     // 2H

// ---------------- device scratch ----------------
__device__ float g_bufA[(size_t)BB * HH * LL];            // layer input (B,H,L) fp32
__device__ float4 g_wc4[(size_t)NLAYERS * HH * NS * 4];   // per-state consts (w^1..4, 2C w^1..4)
__device__ float4 g_kk4[NLAYERS * HH];                    // per-h conv taps K0..K3
__device__ __nv_bfloat16 g_yT_hi[(size_t)BB * LL * HH];   // scan out (B,L,H)
__device__ __nv_bfloat16 g_yT_lo[(size_t)BB * LL * HH];
__device__ __nv_bfloat16 g_xb_hi[(size_t)BB * HH * LL];   // last-layer GLU out (B,H,L)
__device__ __nv_bfloat16 g_xb_lo[(size_t)BB * HH * LL];
__device__ __nv_bfloat16 g_Wo_hi[(size_t)NLAYERS * H2 * HH];
__device__ __nv_bfloat16 g_Wo_lo[(size_t)NLAYERS * H2 * HH];
__device__ __nv_bfloat16 g_Wout_hi[(size_t)PP * LL];
__device__ __nv_bfloat16 g_Wout_lo[(size_t)PP * LL];

// ---------------- PTX helpers ----------------
__device__ __forceinline__ uint32_t smem_u32(const void* p) {
    uint32_t a;
    asm("{ .reg .u64 t; cvta.to.shared.u64 t, %1; cvt.u32.u64 %0, t; }" : "=r"(a) : "l"(p));
    return a;
}
__device__ __forceinline__ void cp_async16(uint32_t smem, const void* g) {
    asm volatile("cp.async.cg.shared.global [%0], [%1], 16;\n" :: "r"(smem), "l"(g));
}
#define CP_COMMIT() asm volatile("cp.async.commit_group;\n" ::: "memory")
#define CP_WAIT(n)  asm volatile("cp.async.wait_group %0;\n" :: "n"(n) : "memory")

__device__ __forceinline__ void ldsm4(uint32_t* r, uint32_t addr) {
    asm volatile("ldmatrix.sync.aligned.m8n8.x4.shared.b16 {%0,%1,%2,%3}, [%4];"
        : "=r"(r[0]), "=r"(r[1]), "=r"(r[2]), "=r"(r[3]) : "r"(addr));
}
__device__ __forceinline__ void mma16816(float* d, const uint32_t* a, const uint32_t* b) {
    asm volatile("mma.sync.aligned.m16n8k16.row.col.f32.bf16.bf16.f32 "
        "{%0,%1,%2,%3}, {%4,%5,%6,%7}, {%8,%9}, {%0,%1,%2,%3};"
        : "+f"(d[0]), "+f"(d[1]), "+f"(d[2]), "+f"(d[3])
        : "r"(a[0]), "r"(a[1]), "r"(a[2]), "r"(a[3]), "r"(b[0]), "r"(b[1]));
}

// ---------------- precompute 4-step SSM constants (fp64, parallel) ----------------
__global__ void prep_kernel(const float* __restrict__ log_dt,
                            const float* __restrict__ A_re,
                            const float* __restrict__ A_im,
                            const float* __restrict__ C_re,
                            const float* __restrict__ C_im)
{
    int gid = blockIdx.x * blockDim.x + threadIdx.x;
    int wrp = gid >> 5, lane = gid & 31;
    if (wrp >= NLAYERS * HH) return;
    int h = wrp % HH, layer = wrp / HH;
    int idx = wrp * NS + lane;

    double dt = exp((double)log_dt[layer * HH + h]);
    double ar = (double)A_re[idx], ai = (double)A_im[idx];
    double er = exp(dt * ar);
    double wre = er * cos(dt * ai), wim = er * sin(dt * ai);
    double mre = wre - 1.0, mim = wim;
    double inv = 1.0 / (ar * ar + ai * ai);
    double fre = (mre * ar + mim * ai) * inv;
    double fim = (mim * ar - mre * ai) * inv;
    double cr = (double)C_re[idx], ci = (double)C_im[idx];
    double ctre = cr * fre - ci * fim, ctim = cr * fim + ci * fre;
    double w2re = wre * wre - wim * wim,   w2im = 2.0 * wre * wim;
    double w3re = w2re * wre - w2im * wim, w3im = w2re * wim + w2im * wre;
    double w4re = w3re * wre - w3im * wim, w4im = w3re * wim + w3im * wre;
    double c1re = 2.0 * (ctre * wre  - ctim * wim),  c1im = 2.0 * (ctre * wim  + ctim * wre);
    double c2re = 2.0 * (ctre * w2re - ctim * w2im), c2im = 2.0 * (ctre * w2im + ctim * w2re);
    double c3re = 2.0 * (ctre * w3re - ctim * w3im), c3im = 2.0 * (ctre * w3im + ctim * w3re);
    double c4re = 2.0 * (ctre * w4re - ctim * w4im), c4im = 2.0 * (ctre * w4im + ctim * w4re);

    size_t base = (size_t)idx * 4;
    g_wc4[base + 0] = make_float4((float)wre,  (float)wim,  (float)w2re, (float)w2im);
    g_wc4[base + 1] = make_float4((float)w3re, (float)w3im, (float)w4re, (float)w4im);
    g_wc4[base + 2] = make_float4((float)c1re, (float)c1im, (float)c2re, (float)c2im);
    g_wc4[base + 3] = make_float4((float)c3re, (float)c3im, (float)c4re, (float)c4im);

    double kk0 = 2.0 * ctre, kk1 = c1re, kk2 = c2re, kk3 = c3re;
#pragma unroll
    for (int off = 16; off >= 1; off >>= 1) {
        kk0 += __shfl_xor_sync(0xffffffffu, kk0, off);
        kk1 += __shfl_xor_sync(0xffffffffu, kk1, off);
        kk2 += __shfl_xor_sync(0xffffffffu, kk2, off);
        kk3 += __shfl_xor_sync(0xffffffffu, kk3, off);
    }
    if (lane == 0)
        g_kk4[wrp] = make_float4((float)kk0, (float)kk1, (float)kk2, (float)kk3);
}

// ---------------- split weights to bf16 hi/lo ----------------
__global__ void wo_conv_kernel(const float* __restrict__ Wo, const float* __restrict__ Wout)
{
    int i = blockIdx.x * blockDim.x + threadIdx.x;
    if (i < NLAYERS * H2 * HH) {
        float v = Wo[i];
        __nv_bfloat16 hi = __float2bfloat16(v);
        g_Wo_hi[i] = hi;
        g_Wo_lo[i] = __float2bfloat16(v - __bfloat162float(hi));
    }
    if (i < PP * LL) {
        float v = Wout[i];
        __nv_bfloat16 hi = __float2bfloat16(v);
        g_Wout_hi[i] = hi;
        g_Wout_lo[i] = __float2bfloat16(v - __bfloat162float(hi));
    }
}

// ---------------- transpose (B,L,E) -> (B,E,L) ----------------
__global__ void transpose_kernel(const float* __restrict__ in)
{
    __shared__ float tile[32][33];
    int b = blockIdx.z;
    int l0 = blockIdx.x * 32, e0 = blockIdx.y * 32;
    int tx = threadIdx.x, ty = threadIdx.y;
#pragma unroll
    for (int j = 0; j < 32; j += 8)
        tile[ty + j][tx] = in[((size_t)b * LL + l0 + ty + j) * EE + e0 + tx];
    __syncthreads();
#pragma unroll
    for (int j = 0; j < 32; j += 8)
        g_bufA[((size_t)b * EE + e0 + ty + j) * LL + l0 + tx] = tile[tx][ty + j];
}

// ---------------- SSM scan: 4-step state hop + butterfly + conv taps ----------------
__global__ __launch_bounds__(256) void scan_kernel(const float* __restrict__ Dskip, int layer)
{
    __shared__ float sT[8][132];
    __shared__ float uS[8][36];
    int tid = threadIdx.x;
    int w = tid >> 5, lane = tid & 31;
    int b  = blockIdx.x >> 6;
    int h0 = (blockIdx.x & 63) * 8;
    int h  = h0 + w;

    size_t cbase = ((size_t)(layer * HH + h) * NS + lane) * 4;
    float4 f0 = g_wc4[cbase + 0];
    float4 f1 = g_wc4[cbase + 1];
    float4 f2 = g_wc4[cbase + 2];
    float4 f3 = g_wc4[cbase + 3];
    const float w1re = f0.x, w1im = f0.y, w2re = f0.z, w2im = f0.w;
    const float w3re = f1.x, w3im = f1.y, w4re = f1.z, w4im = f1.w;
    const float c1re = f2.x, c1im = f2.y, c2re = f2.z, c2im = f2.w;
    const float c3re = f3.x, c3im = f3.y, c4re = f3.z, c4im = f3.w;

    float4 kkv = g_kk4[layer * HH + h];
    float dsk = Dskip[layer * HH + h];
    int m = lane & 3;
    const float ck0 = kkv.x + dsk;
    const float ck1 = (m >= 1) ? kkv.y : 0.f;
    const float ck2 = (m >= 2) ? kkv.z : 0.f;
    const float ck3 = (m >= 3) ? kkv.w : 0.f;

    const float* up = g_bufA + ((size_t)b * HH + h) * LL;

    float Bre = 0.f, Bim = 0.f;
    for (int l0 = 0; l0 < LL; l0 += 128) {
#pragma unroll
        for (int cc = 0; cc < 4; cc++) {
            float um = up[l0 + cc * 32 + lane];
            __syncwarp();
            uS[w][lane] = um;
            __syncwarp();
            float cbuf[32];
#pragma unroll
            for (int q = 0; q < 8; q++) {
                float4 u4 = *(const float4*)&uS[w][q * 4];
                cbuf[q * 4 + 0] = fmaf(c1re, Bre, -c1im * Bim);
                cbuf[q * 4 + 1] = fmaf(c2re, Bre, -c2im * Bim);
                cbuf[q * 4 + 2] = fmaf(c3re, Bre, -c3im * Bim);
                cbuf[q * 4 + 3] = fmaf(c4re, Bre, -c4im * Bim);
                float vre = fmaf(w1re, u4.z, u4.w);
                vre = fmaf(w2re, u4.y, vre);
                vre = fmaf(w3re, u4.x, vre);
                float vim = w1im * u4.z;
                vim = fmaf(w2im, u4.y, vim);
                vim = fmaf(w3im, u4.x, vim);
                float nre = fmaf(w4re, Bre, vre); nre = fmaf(-w4im, Bim, nre);
                float nim = fmaf(w4im, Bre, vim); nim = fmaf(w4re, Bim, nim);
                Bre = nre; Bim = nim;
            }
#pragma unroll
            for (int stage = 0; stage < 5; stage++) {
                const int off = 16 >> stage;
                const int nk  = 16 >> stage;
#pragma unroll
                for (int k = 0; k < nk; k++) {
                    float lo = cbuf[k], hi = cbuf[k + nk];
                    bool upb = (lane & off) != 0;
                    float mine  = upb ? hi : lo;
                    float other = upb ? lo : hi;
                    cbuf[k] = mine + __shfl_xor_sync(0xffffffffu, other, off);
                }
            }
            float u1 = __shfl_up_sync(0xffffffffu, um, 1);
            float u2 = __shfl_up_sync(0xffffffffu, um, 2);
            float u3 = __shfl_up_sync(0xffffffffu, um, 3);
            float yv = fmaf(ck0, um, cbuf[0]);
            yv = fmaf(ck1, u1, yv);
            yv = fmaf(ck2, u2, yv);
            yv = fmaf(ck3, u3, yv);
            float t3 = fmaf(0.044715f * yv * yv, yv, yv);
            float sg = __fdividef(1.0f, 1.0f + __expf(-1.5957691216057308f * t3));
            sT[w][cc * 32 + lane] = yv * sg;
        }
        __syncthreads();
        int hh = tid & 7, lb = tid >> 3;
#pragma unroll
        for (int i = 0; i < 4; i++) {
            int li = lb + i * 32;
            float v = sT[hh][li];
            __nv_bfloat16 hi = __float2bfloat16(v);
            __nv_bfloat16 lo = __float2bfloat16(v - __bfloat162float(hi));
            size_t idx = ((size_t)b * LL + l0 + li) * HH + h0 + hh;
            g_yT_hi[idx] = hi;
            g_yT_lo[idx] = lo;
        }
        __syncthreads();
    }
}

// ---------------- HMMA GLU GEMM ----------------
#define GSTAGE_SZ  98304
#define GLU_SMEM   (1024 + 2 * GSTAGE_SZ)

__global__ __launch_bounds__(256, 1) void glu_mma_kernel(const float* __restrict__ bo,
                                                         int layer, int write_bf16)
{
    extern __shared__ char smem[];
    uint32_t sb = smem_u32(smem);
    const int tid = threadIdx.x;
    const int lane = tid & 31, wid = tid >> 5;
    const int wm = wid & 1, wn = wid >> 1;     // 2 x 4 warp grid
    const int o0 = blockIdx.x * 128;
    const int l0 = blockIdx.y * 128;
    const int b  = blockIdx.z;

    float* sBo = (float*)smem;
    if (tid < 128) sBo[tid] = bo[layer * H2 + o0 + tid];
    else           sBo[tid] = bo[layer * H2 + 512 + o0 + (tid - 128)];

    const __nv_bfloat16* yhi = g_yT_hi + (size_t)b * LL * HH;
    const __nv_bfloat16* ylo = g_yT_lo + (size_t)b * LL * HH;
    const __nv_bfloat16* whi = g_Wo_hi + (size_t)layer * H2 * HH;
    const __nv_bfloat16* wlo = g_Wo_lo + (size_t)layer * H2 * HH;

    uint32_t stBase0 = sb + 1024;

    auto load_chunk = [&](int chunk) {
        uint32_t base = stBase0 + (chunk & 1) * GSTAGE_SZ;
        int kk = chunk * 64;
#pragma unroll
        for (int j = 0; j < 24; j++) {
            int id = tid + 256 * j;
            if (id < 2048) {
                int sp = id >> 10, rm = id & 1023;
                int row = rm >> 3, c = rm & 7;
                const __nv_bfloat16* src = (sp ? ylo : yhi)
                    + (size_t)(l0 + row) * HH + kk + c * 8;
                cp_async16(base + sp * 16384 + row * 128 + ((c ^ (row & 7)) << 4), src);
            } else {
                int i2 = id - 2048;
                int sp = i2 >> 11, rm = i2 & 2047;
                int row = rm >> 3, c = rm & 7;
                int orow = (row < 128) ? (o0 + row) : (512 + o0 + row - 128);
                const __nv_bfloat16* src = (sp ? wlo : whi)
                    + (size_t)orow * HH + kk + c * 8;
                cp_async16(base + 32768 + sp * 32768 + row * 128 + ((c ^ (row & 7)) << 4), src);
            }
        }
        CP_COMMIT();
    };

    float d[4][8][4];
#pragma unroll
    for (int i = 0; i < 4; i++)
#pragma unroll
        for (int j = 0; j < 8; j++)
#pragma unroll
            for (int k = 0; k < 4; k++) d[i][j][k] = 0.f;

    load_chunk(0);
    for (int ch = 0; ch < 8; ch++) {
        if (ch + 1 < 8) { load_chunk(ch + 1); CP_WAIT(1); }
        else            { CP_WAIT(0); }
        __syncthreads();
        uint32_t base = stBase0 + (ch & 1) * GSTAGE_SZ;
#pragma unroll
        for (int kc = 0; kc < 4; kc++) {
            uint32_t ah[4][4], al[4][4];
#pragma unroll
            for (int mf = 0; mf < 4; mf++) {
                int row = wm * 64 + mf * 16 + (lane & 15);
                int cc = 2 * kc + (lane >> 4);
                uint32_t ad = base + row * 128 + ((cc ^ (row & 7)) << 4);
                ldsm4(ah[mf], ad);
                ldsm4(al[mf], ad + 16384);
            }
#pragma unroll
            for (int nf = 0; nf < 4; nf++) {
                int nrow = wn * 64 + nf * 16 + (lane & 7) + ((lane & 16) >> 1);
                int cc = 2 * kc + ((lane >> 3) & 1);
                uint32_t bd = base + 32768 + nrow * 128 + ((cc ^ (nrow & 7)) << 4);
                uint32_t bh[4], bl[4];
                ldsm4(bh, bd);
                ldsm4(bl, bd + 32768);
                // term-major order: 8 independent accumulator chains between reuses
#pragma unroll
                for (int mf = 0; mf < 4; mf++) {
                    mma16816(d[mf][nf * 2],     ah[mf], bh);
                    mma16816(d[mf][nf * 2 + 1], ah[mf], bh + 2);
                }
#pragma unroll
                for (int mf = 0; mf < 4; mf++) {
                    mma16816(d[mf][nf * 2],     ah[mf], bl);
                    mma16816(d[mf][nf * 2 + 1], ah[mf], bl + 2);
                }
#pragma unroll
                for (int mf = 0; mf < 4; mf++) {
                    mma16816(d[mf][nf * 2],     al[mf], bh);
                    mma16816(d[mf][nf * 2 + 1], al[mf], bh + 2);
                }
            }
        }
        __syncthreads();
    }

    // ---- epilogue ----
    float* sC = (float*)(smem + 1024);      // 256 x 132 fp32
    {
        int r  = lane >> 2;
        int c2 = (lane & 3) * 2;
#pragma unroll
        for (int mf = 0; mf < 4; mf++)
#pragma unroll
            for (int nf8 = 0; nf8 < 8; nf8++) {
                int l = wm * 64 + mf * 16 + r;
                int o = wn * 64 + nf8 * 8 + c2;
                sC[o * 132 + l]             = d[mf][nf8][0];
                sC[(o + 1) * 132 + l]       = d[mf][nf8][1];
                sC[o * 132 + l + 8]         = d[mf][nf8][2];
                sC[(o + 1) * 132 + l + 8]   = d[mf][nf8][3];
            }
    }
    __syncthreads();

    int l = tid & 127;
    for (int j = tid >> 7; j < 128; j += 2) {
        float z1 = sC[j * 132 + l] + sBo[j];
        float z2 = sC[(j + 128) * 132 + l] + sBo[128 + j];
        float v = z1 * __fdividef(1.0f, 1.0f + __expf(-z2));
        size_t idx = ((size_t)b * HH + o0 + j) * LL + l0 + l;
        if (write_bf16) {
            __nv_bfloat16 hi = __float2bfloat16(v);
            g_xb_hi[idx] = hi;
            g_xb_lo[idx] = __float2bfloat16(v - __bfloat162float(hi));
        } else {
            g_bufA[idx] = v;
        }
    }
}

// ---------------- HMMA output GEMM: out[b,p,h] = b_out[p] + sum_l W[p,l] x[b,h,l] ----------------
#define OSTAGE_SZ 65536     // Whi 16K | Wlo 16K | Xhi 16K | Xlo 16K
#define OUT_SMEM  (1024 + 2 * OSTAGE_SZ)

__global__ __launch_bounds__(256, 1) void out_mma_kernel(const float* __restrict__ bout,
                                                         float* __restrict__ out)
{
    extern __shared__ char smem[];
    uint32_t sb = smem_u32(smem);
    const int tid = threadIdx.x;
    const int lane = tid & 31, wid = tid >> 5;
    const int wm = wid & 1, wn = wid >> 1;     // 2 x 4
    const int p0 = blockIdx.x * 128;
    const int h0 = blockIdx.y * 128;
    const int b  = blockIdx.z;

    const __nv_bfloat16* xhi = g_xb_hi + (size_t)b * HH * LL;
    const __nv_bfloat16* xlo = g_xb_lo + (size_t)b * HH * LL;

    uint32_t stBase0 = sb + 1024;

    auto load_chunk = [&](int chunk) {
        uint32_t base = stBase0 + (chunk & 1) * OSTAGE_SZ;
        int kk = chunk * 64;
#pragma unroll
        for (int j = 0; j < 16; j++) {
            int id = tid + 256 * j;
            int sp = (id >> 10) & 1;            // hi/lo
            int rm = id & 1023;
            int row = rm >> 3, c = rm & 7;
            uint32_t dst = base + (id >> 11) * 32768 + sp * 16384
                         + row * 128 + ((c ^ (row & 7)) << 4);
            if (id < 2048) {
                int p = p0 + row; if (p >= PP) p = PP - 1;
                const __nv_bfloat16* src = (sp ? g_Wout_lo : g_Wout_hi)
                    + (size_t)p * LL + kk + c * 8;
                cp_async16(dst, src);
            } else {
                const __nv_bfloat16* src = (sp ? xlo : xhi)
                    + (size_t)(h0 + row) * LL + kk + c * 8;
                cp_async16(dst, src);
            }
        }
        CP_COMMIT();
    };

    float d[4][4][4];
#pragma unroll
    for (int i = 0; i < 4; i++)
#pragma unroll
        for (int j = 0; j < 4; j++)
#pragma unroll
            for (int k = 0; k < 4; k++) d[i][j][k] = 0.f;

    load_chunk(0);
    for (int ch = 0; ch < 16; ch++) {
        if (ch + 1 < 16) { load_chunk(ch + 1); CP_WAIT(1); }
        else             { CP_WAIT(0); }
        __syncthreads();
        uint32_t base = stBase0 + (ch & 1) * OSTAGE_SZ;
#pragma unroll
        for (int kc = 0; kc < 4; kc++) {
            uint32_t ah[4][4], al[4][4];
#pragma unroll
            for (int mf = 0; mf < 4; mf++) {
                int row = wm * 64 + mf * 16 + (lane & 15);
                int cc = 2 * kc + (lane >> 4);
                uint32_t ad = base + row * 128 + ((cc ^ (row & 7)) << 4);
                ldsm4(ah[mf], ad);
                ldsm4(al[mf], ad + 16384);
            }
#pragma unroll
            for (int nf = 0; nf < 2; nf++) {
                int nrow = wn * 32 + nf * 16 + (lane & 7) + ((lane & 16) >> 1);
                int cc = 2 * kc + ((lane >> 3) & 1);
                uint32_t bd = base + 32768 + nrow * 128 + ((cc ^ (nrow & 7)) << 4);
                uint32_t bh[4], bl[4];
                ldsm4(bh, bd);
                ldsm4(bl, bd + 16384);
                // term-major order
#pragma unroll
                for (int mf = 0; mf < 4; mf++) {
                    mma16816(d[mf][nf * 2],     ah[mf], bh);
                    mma16816(d[mf][nf * 2 + 1], ah[mf], bh + 2);
                }
#pragma unroll
                for (int mf = 0; mf < 4; mf++) {
                    mma16816(d[mf][nf * 2],     ah[mf], bl);
                    mma16816(d[mf][nf * 2 + 1], ah[mf], bl + 2);
                }
#pragma unroll
                for (int mf = 0; mf < 4; mf++) {
                    mma16816(d[mf][nf * 2],     al[mf], bh);
                    mma16816(d[mf][nf * 2 + 1], al[mf], bh + 2);
                }
            }
        }
        __syncthreads();
    }

    float* sC = (float*)(smem + 1024);   // 128 x 136
    {
        int r  = lane >> 2;
        int c2 = (lane & 3) * 2;
#pragma unroll
        for (int mf = 0; mf < 4; mf++)
#pragma unroll
            for (int nf8 = 0; nf8 < 4; nf8++) {
                int p = wm * 64 + mf * 16 + r;
                int h = wn * 32 + nf8 * 8 + c2;
                sC[p * 136 + h]           = d[mf][nf8][0];
                sC[p * 136 + h + 1]       = d[mf][nf8][1];
                sC[(p + 8) * 136 + h]     = d[mf][nf8][2];
                sC[(p + 8) * 136 + h + 1] = d[mf][nf8][3];
            }
    }
    __syncthreads();

    int hl = tid & 127;
    for (int p = tid >> 7; p < 128; p += 2) {
        int pg = p0 + p;
        if (pg < PP) {
            float v = sC[p * 136 + hl] + __ldg(&bout[pg]);
            out[((size_t)b * PP + pg) * EE + h0 + hl] = v;
        }
    }
}

// ---------------- launch ----------------
extern "C" void kernel_launch(void* const* d_in, const int* in_sizes, int n_in,
                              void* d_out, int out_size)
{
    const float* x_enc  = (const float*)d_in[0];
    const float* log_dt = (const float*)d_in[4];
    const float* A_re   = (const float*)d_in[5];
    const float* A_im   = (const float*)d_in[6];
    const float* C_re   = (const float*)d_in[7];
    const float* C_im   = (const float*)d_in[8];
    const float* Dskip  = (const float*)d_in[9];
    const float* Wo     = (const float*)d_in[10];
    const float* bo     = (const float*)d_in[11];
    const float* W_out  = (const float*)d_in[12];
    const float* b_out  = (const float*)d_in[13];
    float* out = (float*)d_out;

    cudaFuncSetAttribute(glu_mma_kernel,
                         cudaFuncAttributeMaxDynamicSharedMemorySize, GLU_SMEM);
    cudaFuncSetAttribute(out_mma_kernel,
                         cudaFuncAttributeMaxDynamicSharedMemorySize, OUT_SMEM);

    {
        int n = NLAYERS * HH * NS;
        prep_kernel<<<(n + 255) / 256, 256>>>(log_dt, A_re, A_im, C_re, C_im);
    }
    {
        int n = NLAYERS * H2 * HH;
        wo_conv_kernel<<<(n + 255) / 256, 256>>>(Wo, W_out);
    }
    {
        dim3 grid(LL / 32, EE / 32, BB);
        dim3 block(32, 8);
        transpose_kernel<<<grid, block>>>(x_enc);
    }
    for (int layer = 0; layer < NLAYERS; layer++) {
        scan_kernel<<<BB * HH / 8, 256>>>(Dskip, layer);
        dim3 grid(4, 8, BB);
        glu_mma_kernel<<<grid, 256, GLU_SMEM>>>(bo, layer, layer == NLAYERS - 1);
    }
    {
        dim3 grid(3, 4, BB);
        out_mma_kernel<<<grid, 256, OUT_SMEM>>>(b_out, out);
    }
}

// round 15
// speedup vs baseline: 1.0042x; 1.0042x over previous
#include <cuda_runtime.h>
#include <cuda_bf16.h>
#include <math.h>
#include <stdint.h>

// Problem constants
#define BB 32
#define LL 1024
#define EE 512      // H
#define PP 336
#define NLAYERS 3
#define NS 32
#define HH 512
#define H2 1024     // 2H

// ---------------- device scratch ----------------
__device__ float g_bufA[(size_t)BB * HH * LL];            // layer input (B,H,L) fp32
__device__ float4 g_wc4[(size_t)NLAYERS * HH * NS * 4];   // per-state consts (w^1..4, 2C w^1..4)
__device__ float4 g_kk4[NLAYERS * HH];                    // per-h conv taps K0..K3
__device__ __nv_bfloat16 g_yT_hi[(size_t)BB * LL * HH];   // scan out (B,L,H)
__device__ __nv_bfloat16 g_yT_lo[(size_t)BB * LL * HH];
__device__ __nv_bfloat16 g_xb_hi[(size_t)BB * HH * LL];   // last-layer GLU out (B,H,L)
__device__ __nv_bfloat16 g_xb_lo[(size_t)BB * HH * LL];
__device__ __nv_bfloat16 g_Wo_hi[(size_t)NLAYERS * H2 * HH];
__device__ __nv_bfloat16 g_Wo_lo[(size_t)NLAYERS * H2 * HH];
__device__ __nv_bfloat16 g_Wout_hi[(size_t)PP * LL];
__device__ __nv_bfloat16 g_Wout_lo[(size_t)PP * LL];

// ---------------- PTX helpers ----------------
__device__ __forceinline__ uint32_t smem_u32(const void* p) {
    uint32_t a;
    asm("{ .reg .u64 t; cvta.to.shared.u64 t, %1; cvt.u32.u64 %0, t; }" : "=r"(a) : "l"(p));
    return a;
}
__device__ __forceinline__ void cp_async16(uint32_t smem, const void* g) {
    asm volatile("cp.async.cg.shared.global [%0], [%1], 16;\n" :: "r"(smem), "l"(g));
}
#define CP_COMMIT() asm volatile("cp.async.commit_group;\n" ::: "memory")
#define CP_WAIT(n)  asm volatile("cp.async.wait_group %0;\n" :: "n"(n) : "memory")

__device__ __forceinline__ void ldsm4(uint32_t* r, uint32_t addr) {
    asm volatile("ldmatrix.sync.aligned.m8n8.x4.shared.b16 {%0,%1,%2,%3}, [%4];"
        : "=r"(r[0]), "=r"(r[1]), "=r"(r[2]), "=r"(r[3]) : "r"(addr));
}
__device__ __forceinline__ void mma16816(float* d, const uint32_t* a, const uint32_t* b) {
    asm volatile("mma.sync.aligned.m16n8k16.row.col.f32.bf16.bf16.f32 "
        "{%0,%1,%2,%3}, {%4,%5,%6,%7}, {%8,%9}, {%0,%1,%2,%3};"
        : "+f"(d[0]), "+f"(d[1]), "+f"(d[2]), "+f"(d[3])
        : "r"(a[0]), "r"(a[1]), "r"(a[2]), "r"(a[3]), "r"(b[0]), "r"(b[1]));
}

// ---------------- precompute 4-step SSM constants (fp64, parallel) ----------------
__global__ void prep_kernel(const float* __restrict__ log_dt,
                            const float* __restrict__ A_re,
                            const float* __restrict__ A_im,
                            const float* __restrict__ C_re,
                            const float* __restrict__ C_im)
{
    int gid = blockIdx.x * blockDim.x + threadIdx.x;
    int wrp = gid >> 5, lane = gid & 31;
    if (wrp >= NLAYERS * HH) return;
    int h = wrp % HH, layer = wrp / HH;
    int idx = wrp * NS + lane;

    double dt = exp((double)log_dt[layer * HH + h]);
    double ar = (double)A_re[idx], ai = (double)A_im[idx];
    double er = exp(dt * ar);
    double wre = er * cos(dt * ai), wim = er * sin(dt * ai);
    double mre = wre - 1.0, mim = wim;
    double inv = 1.0 / (ar * ar + ai * ai);
    double fre = (mre * ar + mim * ai) * inv;
    double fim = (mim * ar - mre * ai) * inv;
    double cr = (double)C_re[idx], ci = (double)C_im[idx];
    double ctre = cr * fre - ci * fim, ctim = cr * fim + ci * fre;
    double w2re = wre * wre - wim * wim,   w2im = 2.0 * wre * wim;
    double w3re = w2re * wre - w2im * wim, w3im = w2re * wim + w2im * wre;
    double w4re = w3re * wre - w3im * wim, w4im = w3re * wim + w3im * wre;
    double c1re = 2.0 * (ctre * wre  - ctim * wim),  c1im = 2.0 * (ctre * wim  + ctim * wre);
    double c2re = 2.0 * (ctre * w2re - ctim * w2im), c2im = 2.0 * (ctre * w2im + ctim * w2re);
    double c3re = 2.0 * (ctre * w3re - ctim * w3im), c3im = 2.0 * (ctre * w3im + ctim * w3re);
    double c4re = 2.0 * (ctre * w4re - ctim * w4im), c4im = 2.0 * (ctre * w4im + ctim * w4re);

    size_t base = (size_t)idx * 4;
    g_wc4[base + 0] = make_float4((float)wre,  (float)wim,  (float)w2re, (float)w2im);
    g_wc4[base + 1] = make_float4((float)w3re, (float)w3im, (float)w4re, (float)w4im);
    g_wc4[base + 2] = make_float4((float)c1re, (float)c1im, (float)c2re, (float)c2im);
    g_wc4[base + 3] = make_float4((float)c3re, (float)c3im, (float)c4re, (float)c4im);

    double kk0 = 2.0 * ctre, kk1 = c1re, kk2 = c2re, kk3 = c3re;
#pragma unroll
    for (int off = 16; off >= 1; off >>= 1) {
        kk0 += __shfl_xor_sync(0xffffffffu, kk0, off);
        kk1 += __shfl_xor_sync(0xffffffffu, kk1, off);
        kk2 += __shfl_xor_sync(0xffffffffu, kk2, off);
        kk3 += __shfl_xor_sync(0xffffffffu, kk3, off);
    }
    if (lane == 0)
        g_kk4[wrp] = make_float4((float)kk0, (float)kk1, (float)kk2, (float)kk3);
}

// ---------------- split weights to bf16 hi/lo ----------------
__global__ void wo_conv_kernel(const float* __restrict__ Wo, const float* __restrict__ Wout)
{
    int i = blockIdx.x * blockDim.x + threadIdx.x;
    if (i < NLAYERS * H2 * HH) {
        float v = Wo[i];
        __nv_bfloat16 hi = __float2bfloat16(v);
        g_Wo_hi[i] = hi;
        g_Wo_lo[i] = __float2bfloat16(v - __bfloat162float(hi));
    }
    if (i < PP * LL) {
        float v = Wout[i];
        __nv_bfloat16 hi = __float2bfloat16(v);
        g_Wout_hi[i] = hi;
        g_Wout_lo[i] = __float2bfloat16(v - __bfloat162float(hi));
    }
}

// ---------------- transpose (B,L,E) -> (B,E,L) ----------------
__global__ void transpose_kernel(const float* __restrict__ in)
{
    __shared__ float tile[32][33];
    int b = blockIdx.z;
    int l0 = blockIdx.x * 32, e0 = blockIdx.y * 32;
    int tx = threadIdx.x, ty = threadIdx.y;
#pragma unroll
    for (int j = 0; j < 32; j += 8)
        tile[ty + j][tx] = in[((size_t)b * LL + l0 + ty + j) * EE + e0 + tx];
    __syncthreads();
#pragma unroll
    for (int j = 0; j < 32; j += 8)
        g_bufA[((size_t)b * EE + e0 + ty + j) * LL + l0 + tx] = tile[tx][ty + j];
}

// ---------------- SSM scan: 4-step state hop + butterfly + conv taps ----------------
__global__ __launch_bounds__(256) void scan_kernel(const float* __restrict__ Dskip, int layer)
{
    __shared__ float sT[8][132];
    __shared__ float uS[8][36];
    int tid = threadIdx.x;
    int w = tid >> 5, lane = tid & 31;
    int b  = blockIdx.x >> 6;
    int h0 = (blockIdx.x & 63) * 8;
    int h  = h0 + w;

    size_t cbase = ((size_t)(layer * HH + h) * NS + lane) * 4;
    float4 f0 = g_wc4[cbase + 0];
    float4 f1 = g_wc4[cbase + 1];
    float4 f2 = g_wc4[cbase + 2];
    float4 f3 = g_wc4[cbase + 3];
    const float w1re = f0.x, w1im = f0.y, w2re = f0.z, w2im = f0.w;
    const float w3re = f1.x, w3im = f1.y, w4re = f1.z, w4im = f1.w;
    const float c1re = f2.x, c1im = f2.y, c2re = f2.z, c2im = f2.w;
    const float c3re = f3.x, c3im = f3.y, c4re = f3.z, c4im = f3.w;

    float4 kkv = g_kk4[layer * HH + h];
    float dsk = Dskip[layer * HH + h];
    int m = lane & 3;
    const float ck0 = kkv.x + dsk;
    const float ck1 = (m >= 1) ? kkv.y : 0.f;
    const float ck2 = (m >= 2) ? kkv.z : 0.f;
    const float ck3 = (m >= 3) ? kkv.w : 0.f;

    const float* up = g_bufA + ((size_t)b * HH + h) * LL;

    float Bre = 0.f, Bim = 0.f;
    for (int l0 = 0; l0 < LL; l0 += 128) {
#pragma unroll
        for (int cc = 0; cc < 4; cc++) {
            float um = up[l0 + cc * 32 + lane];
            __syncwarp();
            uS[w][lane] = um;
            __syncwarp();
            float cbuf[32];
#pragma unroll
            for (int q = 0; q < 8; q++) {
                float4 u4 = *(const float4*)&uS[w][q * 4];
                cbuf[q * 4 + 0] = fmaf(c1re, Bre, -c1im * Bim);
                cbuf[q * 4 + 1] = fmaf(c2re, Bre, -c2im * Bim);
                cbuf[q * 4 + 2] = fmaf(c3re, Bre, -c3im * Bim);
                cbuf[q * 4 + 3] = fmaf(c4re, Bre, -c4im * Bim);
                float vre = fmaf(w1re, u4.z, u4.w);
                vre = fmaf(w2re, u4.y, vre);
                vre = fmaf(w3re, u4.x, vre);
                float vim = w1im * u4.z;
                vim = fmaf(w2im, u4.y, vim);
                vim = fmaf(w3im, u4.x, vim);
                float nre = fmaf(w4re, Bre, vre); nre = fmaf(-w4im, Bim, nre);
                float nim = fmaf(w4im, Bre, vim); nim = fmaf(w4re, Bim, nim);
                Bre = nre; Bim = nim;
            }
#pragma unroll
            for (int stage = 0; stage < 5; stage++) {
                const int off = 16 >> stage;
                const int nk  = 16 >> stage;
#pragma unroll
                for (int k = 0; k < nk; k++) {
                    float lo = cbuf[k], hi = cbuf[k + nk];
                    bool upb = (lane & off) != 0;
                    float mine  = upb ? hi : lo;
                    float other = upb ? lo : hi;
                    cbuf[k] = mine + __shfl_xor_sync(0xffffffffu, other, off);
                }
            }
            float u1 = __shfl_up_sync(0xffffffffu, um, 1);
            float u2 = __shfl_up_sync(0xffffffffu, um, 2);
            float u3 = __shfl_up_sync(0xffffffffu, um, 3);
            float yv = fmaf(ck0, um, cbuf[0]);
            yv = fmaf(ck1, u1, yv);
            yv = fmaf(ck2, u2, yv);
            yv = fmaf(ck3, u3, yv);
            float t3 = fmaf(0.044715f * yv * yv, yv, yv);
            float sg = __fdividef(1.0f, 1.0f + __expf(-1.5957691216057308f * t3));
            sT[w][cc * 32 + lane] = yv * sg;
        }
        __syncthreads();
        int hh = tid & 7, lb = tid >> 3;
#pragma unroll
        for (int i = 0; i < 4; i++) {
            int li = lb + i * 32;
            float v = sT[hh][li];
            __nv_bfloat16 hi = __float2bfloat16(v);
            __nv_bfloat16 lo = __float2bfloat16(v - __bfloat162float(hi));
            size_t idx = ((size_t)b * LL + l0 + li) * HH + h0 + hh;
            g_yT_hi[idx] = hi;
            g_yT_lo[idx] = lo;
        }
        __syncthreads();
    }
}

// ---------------- HMMA GLU GEMM ----------------
#define GSTAGE_SZ  98304
#define GLU_SMEM   (1024 + 2 * GSTAGE_SZ)

__global__ __launch_bounds__(256, 1) void glu_mma_kernel(const float* __restrict__ bo,
                                                         int layer, int write_bf16)
{
    extern __shared__ char smem[];
    uint32_t sb = smem_u32(smem);
    const int tid = threadIdx.x;
    const int lane = tid & 31, wid = tid >> 5;
    const int wm = wid & 1, wn = wid >> 1;     // 2 x 4 warp grid
    const int o0 = blockIdx.x * 128;
    const int l0 = blockIdx.y * 128;
    const int b  = blockIdx.z;

    float* sBo = (float*)smem;
    if (tid < 128) sBo[tid] = bo[layer * H2 + o0 + tid];
    else           sBo[tid] = bo[layer * H2 + 512 + o0 + (tid - 128)];

    const __nv_bfloat16* yhi = g_yT_hi + (size_t)b * LL * HH;
    const __nv_bfloat16* ylo = g_yT_lo + (size_t)b * LL * HH;
    const __nv_bfloat16* whi = g_Wo_hi + (size_t)layer * H2 * HH;
    const __nv_bfloat16* wlo = g_Wo_lo + (size_t)layer * H2 * HH;

    uint32_t stBase0 = sb + 1024;

    auto load_chunk = [&](int chunk) {
        uint32_t base = stBase0 + (chunk & 1) * GSTAGE_SZ;
        int kk = chunk * 64;
#pragma unroll
        for (int j = 0; j < 24; j++) {
            int id = tid + 256 * j;
            if (id < 2048) {
                int sp = id >> 10, rm = id & 1023;
                int row = rm >> 3, c = rm & 7;
                const __nv_bfloat16* src = (sp ? ylo : yhi)
                    + (size_t)(l0 + row) * HH + kk + c * 8;
                cp_async16(base + sp * 16384 + row * 128 + ((c ^ (row & 7)) << 4), src);
            } else {
                int i2 = id - 2048;
                int sp = i2 >> 11, rm = i2 & 2047;
                int row = rm >> 3, c = rm & 7;
                int orow = (row < 128) ? (o0 + row) : (512 + o0 + row - 128);
                const __nv_bfloat16* src = (sp ? wlo : whi)
                    + (size_t)orow * HH + kk + c * 8;
                cp_async16(base + 32768 + sp * 32768 + row * 128 + ((c ^ (row & 7)) << 4), src);
            }
        }
        CP_COMMIT();
    };

    float d[4][8][4];
#pragma unroll
    for (int i = 0; i < 4; i++)
#pragma unroll
        for (int j = 0; j < 8; j++)
#pragma unroll
            for (int k = 0; k < 4; k++) d[i][j][k] = 0.f;

    const int nrow_base = wn * 64 + (lane & 7) + ((lane & 16) >> 1);

    load_chunk(0);
    for (int ch = 0; ch < 8; ch++) {
        if (ch + 1 < 8) { load_chunk(ch + 1); CP_WAIT(1); }
        else            { CP_WAIT(0); }
        __syncthreads();
        uint32_t base = stBase0 + (ch & 1) * GSTAGE_SZ;
#pragma unroll
        for (int kc = 0; kc < 4; kc++) {
            const int ccB = 2 * kc + ((lane >> 3) & 1);
            uint32_t ah[4][4], al[4][4];
#pragma unroll
            for (int mf = 0; mf < 4; mf++) {
                int row = wm * 64 + mf * 16 + (lane & 15);
                int cc = 2 * kc + (lane >> 4);
                uint32_t ad = base + row * 128 + ((cc ^ (row & 7)) << 4);
                ldsm4(ah[mf], ad);
                ldsm4(al[mf], ad + 16384);
            }
            // software-pipelined B fragments (double buffer, 1 nf-step ahead)
            uint32_t bhA[4], blA[4], bhB[4], blB[4];
            {
                int nrow = nrow_base;
                uint32_t bd = base + 32768 + nrow * 128 + ((ccB ^ (nrow & 7)) << 4);
                ldsm4(bhA, bd);
                ldsm4(blA, bd + 32768);
            }
#pragma unroll
            for (int nf = 0; nf < 4; nf++) {
                uint32_t* bh = (nf & 1) ? bhB : bhA;
                uint32_t* bl = (nf & 1) ? blB : blA;
                if (nf < 3) {
                    int nrow = nrow_base + (nf + 1) * 16;
                    uint32_t bd = base + 32768 + nrow * 128 + ((ccB ^ (nrow & 7)) << 4);
                    uint32_t* nbh = (nf & 1) ? bhA : bhB;
                    uint32_t* nbl = (nf & 1) ? blA : blB;
                    ldsm4(nbh, bd);
                    ldsm4(nbl, bd + 32768);
                }
#pragma unroll
                for (int mf = 0; mf < 4; mf++) {
                    mma16816(d[mf][nf * 2],     ah[mf], bh);
                    mma16816(d[mf][nf * 2 + 1], ah[mf], bh + 2);
                }
#pragma unroll
                for (int mf = 0; mf < 4; mf++) {
                    mma16816(d[mf][nf * 2],     ah[mf], bl);
                    mma16816(d[mf][nf * 2 + 1], ah[mf], bl + 2);
                }
#pragma unroll
                for (int mf = 0; mf < 4; mf++) {
                    mma16816(d[mf][nf * 2],     al[mf], bh);
                    mma16816(d[mf][nf * 2 + 1], al[mf], bh + 2);
                }
            }
        }
        __syncthreads();
    }

    // ---- epilogue ----
    float* sC = (float*)(smem + 1024);      // 256 x 132 fp32
    {
        int r  = lane >> 2;
        int c2 = (lane & 3) * 2;
#pragma unroll
        for (int mf = 0; mf < 4; mf++)
#pragma unroll
            for (int nf8 = 0; nf8 < 8; nf8++) {
                int l = wm * 64 + mf * 16 + r;
                int o = wn * 64 + nf8 * 8 + c2;
                sC[o * 132 + l]             = d[mf][nf8][0];
                sC[(o + 1) * 132 + l]       = d[mf][nf8][1];
                sC[o * 132 + l + 8]         = d[mf][nf8][2];
                sC[(o + 1) * 132 + l + 8]   = d[mf][nf8][3];
            }
    }
    __syncthreads();

    int l = tid & 127;
    for (int j = tid >> 7; j < 128; j += 2) {
        float z1 = sC[j * 132 + l] + sBo[j];
        float z2 = sC[(j + 128) * 132 + l] + sBo[128 + j];
        float v = z1 * __fdividef(1.0f, 1.0f + __expf(-z2));
        size_t idx = ((size_t)b * HH + o0 + j) * LL + l0 + l;
        if (write_bf16) {
            __nv_bfloat16 hi = __float2bfloat16(v);
            g_xb_hi[idx] = hi;
            g_xb_lo[idx] = __float2bfloat16(v - __bfloat162float(hi));
        } else {
            g_bufA[idx] = v;
        }
    }
}

// ---------------- HMMA output GEMM: out[b,p,h] = b_out[p] + sum_l W[p,l] x[b,h,l] ----------------
#define OSTAGE_SZ 65536     // Whi 16K | Wlo 16K | Xhi 16K | Xlo 16K
#define OUT_SMEM  (1024 + 2 * OSTAGE_SZ)

__global__ __launch_bounds__(256, 1) void out_mma_kernel(const float* __restrict__ bout,
                                                         float* __restrict__ out)
{
    extern __shared__ char smem[];
    uint32_t sb = smem_u32(smem);
    const int tid = threadIdx.x;
    const int lane = tid & 31, wid = tid >> 5;
    const int wm = wid & 1, wn = wid >> 1;     // 2 x 4
    const int p0 = blockIdx.x * 128;
    const int h0 = blockIdx.y * 128;
    const int b  = blockIdx.z;

    const __nv_bfloat16* xhi = g_xb_hi + (size_t)b * HH * LL;
    const __nv_bfloat16* xlo = g_xb_lo + (size_t)b * HH * LL;

    uint32_t stBase0 = sb + 1024;

    auto load_chunk = [&](int chunk) {
        uint32_t base = stBase0 + (chunk & 1) * OSTAGE_SZ;
        int kk = chunk * 64;
#pragma unroll
        for (int j = 0; j < 16; j++) {
            int id = tid + 256 * j;
            int sp = (id >> 10) & 1;            // hi/lo
            int rm = id & 1023;
            int row = rm >> 3, c = rm & 7;
            uint32_t dst = base + (id >> 11) * 32768 + sp * 16384
                         + row * 128 + ((c ^ (row & 7)) << 4);
            if (id < 2048) {
                int p = p0 + row; if (p >= PP) p = PP - 1;
                const __nv_bfloat16* src = (sp ? g_Wout_lo : g_Wout_hi)
                    + (size_t)p * LL + kk + c * 8;
                cp_async16(dst, src);
            } else {
                const __nv_bfloat16* src = (sp ? xlo : xhi)
                    + (size_t)(h0 + row) * LL + kk + c * 8;
                cp_async16(dst, src);
            }
        }
        CP_COMMIT();
    };

    float d[4][4][4];
#pragma unroll
    for (int i = 0; i < 4; i++)
#pragma unroll
        for (int j = 0; j < 4; j++)
#pragma unroll
            for (int k = 0; k < 4; k++) d[i][j][k] = 0.f;

    const int nrow_base = wn * 32 + (lane & 7) + ((lane & 16) >> 1);

    load_chunk(0);
    for (int ch = 0; ch < 16; ch++) {
        if (ch + 1 < 16) { load_chunk(ch + 1); CP_WAIT(1); }
        else             { CP_WAIT(0); }
        __syncthreads();
        uint32_t base = stBase0 + (ch & 1) * OSTAGE_SZ;
#pragma unroll
        for (int kc = 0; kc < 4; kc++) {
            const int ccB = 2 * kc + ((lane >> 3) & 1);
            uint32_t ah[4][4], al[4][4];
#pragma unroll
            for (int mf = 0; mf < 4; mf++) {
                int row = wm * 64 + mf * 16 + (lane & 15);
                int cc = 2 * kc + (lane >> 4);
                uint32_t ad = base + row * 128 + ((cc ^ (row & 7)) << 4);
                ldsm4(ah[mf], ad);
                ldsm4(al[mf], ad + 16384);
            }
            uint32_t bhA[4], blA[4], bhB[4], blB[4];
            {
                int nrow = nrow_base;
                uint32_t bd = base + 32768 + nrow * 128 + ((ccB ^ (nrow & 7)) << 4);
                ldsm4(bhA, bd);
                ldsm4(blA, bd + 16384);
            }
#pragma unroll
            for (int nf = 0; nf < 2; nf++) {
                uint32_t* bh = (nf & 1) ? bhB : bhA;
                uint32_t* bl = (nf & 1) ? blB : blA;
                if (nf < 1) {
                    int nrow = nrow_base + 16;
                    uint32_t bd = base + 32768 + nrow * 128 + ((ccB ^ (nrow & 7)) << 4);
                    ldsm4(bhB, bd);
                    ldsm4(blB, bd + 16384);
                }
#pragma unroll
                for (int mf = 0; mf < 4; mf++) {
                    mma16816(d[mf][nf * 2],     ah[mf], bh);
                    mma16816(d[mf][nf * 2 + 1], ah[mf], bh + 2);
                }
#pragma unroll
                for (int mf = 0; mf < 4; mf++) {
                    mma16816(d[mf][nf * 2],     ah[mf], bl);
                    mma16816(d[mf][nf * 2 + 1], ah[mf], bl + 2);
                }
#pragma unroll
                for (int mf = 0; mf < 4; mf++) {
                    mma16816(d[mf][nf * 2],     al[mf], bh);
                    mma16816(d[mf][nf * 2 + 1], al[mf], bh + 2);
                }
            }
        }
        __syncthreads();
    }

    float* sC = (float*)(smem + 1024);   // 128 x 136
    {
        int r  = lane >> 2;
        int c2 = (lane & 3) * 2;
#pragma unroll
        for (int mf = 0; mf < 4; mf++)
#pragma unroll
            for (int nf8 = 0; nf8 < 4; nf8++) {
                int p = wm * 64 + mf * 16 + r;
                int h = wn * 32 + nf8 * 8 + c2;
                sC[p * 136 + h]           = d[mf][nf8][0];
                sC[p * 136 + h + 1]       = d[mf][nf8][1];
                sC[(p + 8) * 136 + h]     = d[mf][nf8][2];
                sC[(p + 8) * 136 + h + 1] = d[mf][nf8][3];
            }
    }
    __syncthreads();

    int hl = tid & 127;
    for (int p = tid >> 7; p < 128; p += 2) {
        int pg = p0 + p;
        if (pg < PP) {
            float v = sC[p * 136 + hl] + __ldg(&bout[pg]);
            out[((size_t)b * PP + pg) * EE + h0 + hl] = v;
        }
    }
}

// ---------------- launch ----------------
extern "C" void kernel_launch(void* const* d_in, const int* in_sizes, int n_in,
                              void* d_out, int out_size)
{
    const float* x_enc  = (const float*)d_in[0];
    const float* log_dt = (const float*)d_in[4];
    const float* A_re   = (const float*)d_in[5];
    const float* A_im   = (const float*)d_in[6];
    const float* C_re   = (const float*)d_in[7];
    const float* C_im   = (const float*)d_in[8];
    const float* Dskip  = (const float*)d_in[9];
    const float* Wo     = (const float*)d_in[10];
    const float* bo     = (const float*)d_in[11];
    const float* W_out  = (const float*)d_in[12];
    const float* b_out  = (const float*)d_in[13];
    float* out = (float*)d_out;

    cudaFuncSetAttribute(glu_mma_kernel,
                         cudaFuncAttributeMaxDynamicSharedMemorySize, GLU_SMEM);
    cudaFuncSetAttribute(out_mma_kernel,
                         cudaFuncAttributeMaxDynamicSharedMemorySize, OUT_SMEM);

    {
        int n = NLAYERS * HH * NS;
        prep_kernel<<<(n + 255) / 256, 256>>>(log_dt, A_re, A_im, C_re, C_im);
    }
    {
        int n = NLAYERS * H2 * HH;
        wo_conv_kernel<<<(n + 255) / 256, 256>>>(Wo, W_out);
    }
    {
        dim3 grid(LL / 32, EE / 32, BB);
        dim3 block(32, 8);
        transpose_kernel<<<grid, block>>>(x_enc);
    }
    for (int layer = 0; layer < NLAYERS; layer++) {
        scan_kernel<<<BB * HH / 8, 256>>>(Dskip, layer);
        dim3 grid(4, 8, BB);
        glu_mma_kernel<<<grid, 256, GLU_SMEM>>>(bo, layer, layer == NLAYERS - 1);
    }
    {
        dim3 grid(3, 4, BB);
        out_mma_kernel<<<grid, 256, OUT_SMEM>>>(b_out, out);
    }
}